// round 2
// baseline (speedup 1.0000x reference)
#include <cuda_runtime.h>

// Problem constants (fixed shapes from setup_inputs)
#define NN   50        // N
#define PP   32        // p
#define BB   512       // batch
#define NSQ  2500      // N*N
#define AT   4000
#define FSTRIDE 51     // padded smem row stride (gcd(51,32)=1 -> conflict-free)
#define UNITS_PER_BLOCK 8
#define MAIN_THREADS 512   // 8 units * 64 threads

// ---------------------------------------------------------------------------
// K1: F[i] = sum_j g[i*2500+j] * w[j]^2      (one block per row, 256 threads)
// Rows are 10000 B apart: 8-aligned -> float2 loads are safe, float4 are not.
// ---------------------------------------------------------------------------
__global__ void f_matvec_kernel(const float* __restrict__ g,
                                const float* __restrict__ w,
                                float* __restrict__ Fout) {
    int row = blockIdx.x;
    const float2* grow = (const float2*)(g + (size_t)row * NSQ);
    const float2* w2   = (const float2*)w;
    float acc = 0.f;
    for (int j = threadIdx.x; j < NSQ / 2; j += 256) {
        float2 gv = grow[j];
        float2 wv = w2[j];
        acc = fmaf(gv.x, wv.x * wv.x, acc);
        acc = fmaf(gv.y, wv.y * wv.y, acc);
    }
    #pragma unroll
    for (int o = 16; o > 0; o >>= 1)
        acc += __shfl_down_sync(0xffffffffu, acc, o);
    __shared__ float red[8];
    int warp = threadIdx.x >> 5;
    if ((threadIdx.x & 31) == 0) red[warp] = acc;
    __syncthreads();
    if (threadIdx.x == 0) {
        float s = 0.f;
        #pragma unroll
        for (int k = 0; k < 8; k++) s += red[k];
        Fout[row] = s;
    }
}

// ---------------------------------------------------------------------------
// K2: Z[b,i] = p * mus[y_i[b], i]
// ---------------------------------------------------------------------------
__global__ void init_z_kernel(const int* __restrict__ y_i,
                              const float* __restrict__ mus,
                              float* __restrict__ Z) {
    int idx = blockIdx.x * blockDim.x + threadIdx.x;
    if (idx >= BB * NN) return;
    int b = idx / NN;
    int i = idx - b * NN;
    Z[idx] = (float)PP * mus[y_i[b] * NN + i];
}

// ---------------------------------------------------------------------------
// K3: main. One block = 8 (b,p) units (all same b). Thread = (unit, row i).
//   z[b,p,i] = sum_j exp(-alpha_t * F[i,j]) * a_j  /  sum_j exp(-alpha_t*F[i,j])
//   a_j = x[b, j, p] - mus[t, j],  t = x_i[b,p]
//   Z[b,i] += sum over the 8 units (atomicAdd once per (block,i))
// ---------------------------------------------------------------------------
__global__ __launch_bounds__(MAIN_THREADS)
void main_kernel(const float* __restrict__ x,
                 const int*   __restrict__ x_i,
                 const float* __restrict__ mus,
                 const float* __restrict__ alphas,
                 const float* __restrict__ F,
                 float* __restrict__ Z) {
    __shared__ float Fs[NN * FSTRIDE];
    __shared__ float As[UNITS_PER_BLOCK][NN];
    __shared__ float alpha_s[UNITS_PER_BLOCK];
    __shared__ int   ts[UNITS_PER_BLOCK];
    __shared__ float zred[UNITS_PER_BLOCK * NN];

    int tid  = threadIdx.x;
    int gid0 = blockIdx.x * UNITS_PER_BLOCK;   // first (b,p) unit of this block
    int b    = gid0 >> 5;                      // all 8 units share b (8 | 32)
    int p0   = gid0 & 31;

    // F -> smem with padded stride
    for (int k = tid; k < NSQ; k += MAIN_THREADS) {
        int i = k / NN;
        int j = k - i * NN;
        Fs[i * FSTRIDE + j] = F[k];
    }
    // per-unit t + alpha
    if (tid < UNITS_PER_BLOCK) {
        int t = x_i[gid0 + tid];
        ts[tid] = t;
        alpha_s[tid] = alphas[t];
    }
    __syncthreads();

    // a vectors: k -> (u = k&7, j = k>>3) so consecutive tids hit consecutive p
    for (int k = tid; k < UNITS_PER_BLOCK * NN; k += MAIN_THREADS) {
        int u = k & 7;
        int j = k >> 3;
        As[u][j] = x[(size_t)b * NN * PP + j * PP + p0 + u]
                 - mus[ts[u] * NN + j];
    }
    __syncthreads();

    int u = tid >> 6;       // unit 0..7
    int i = tid & 63;       // row 0..63 (active if < 50)
    if (i < NN) {
        float na = -alpha_s[u];
        const float* frow = &Fs[i * FSTRIDE];
        const float* av   = As[u];
        float acc = 0.f, s = 0.f;
        #pragma unroll
        for (int j = 0; j < NN; j++) {
            float e = __expf(na * frow[j]);
            acc = fmaf(e, av[j], acc);
            s  += e;
        }
        zred[u * NN + i] = __fdividef(acc, s);
    }
    __syncthreads();

    if (tid < NN) {
        float s = 0.f;
        #pragma unroll
        for (int u2 = 0; u2 < UNITS_PER_BLOCK; u2++)
            s += zred[u2 * NN + tid];
        atomicAdd(&Z[b * NN + tid], s);
    }
}

// ---------------------------------------------------------------------------
// launch
// ---------------------------------------------------------------------------
extern "C" void kernel_launch(void* const* d_in, const int* in_sizes, int n_in,
                              void* d_out, int out_size) {
    const float* x      = (const float*)d_in[0];  // [512,50,32]
    const int*   x_i    = (const int*)  d_in[1];  // [512,32]
    const int*   y_i    = (const int*)  d_in[2];  // [512]
    const float* g      = (const float*)d_in[3];  // [2500,2500]
    const float* w      = (const float*)d_in[4];  // [2500,1]
    const float* mus    = (const float*)d_in[5];  // [4000,50]
    const float* alphas = (const float*)d_in[6];  // [4000,1]

    float* out  = (float*)d_out;
    float* Z    = out;             // [512,50] = 25600
    float* Fout = out + BB * NN;   // [2500]

    f_matvec_kernel<<<NSQ, 256>>>(g, w, Fout);
    init_z_kernel<<<(BB * NN + 255) / 256, 256>>>(y_i, mus, Z);
    main_kernel<<<BB * PP / UNITS_PER_BLOCK, MAIN_THREADS>>>(x, x_i, mus, alphas, Fout, Z);
}

// round 4
// speedup vs baseline: 1.0644x; 1.0644x over previous
#include <cuda_runtime.h>

#define NN   50
#define PP   32
#define BB   512
#define NSQ  2500
#define FSTRIDE 51
#define UNITS 10
#define MAIN_THREADS 512
#define TOTAL_UNITS (BB * PP)  // 16384

__device__ __forceinline__ float ex2_approx(float x) {
    float r;
    asm("ex2.approx.f32 %0, %1;" : "=f"(r) : "f"(x));
    return r;
}

// ---------------------------------------------------------------------------
// K1: F[i] = sum_j g[i,j] * w[j]^2.  One warp per row, float4, w^2 in smem.
// Row pitch 10000 B = 625*16 -> every row base is 16B-aligned, float4 legal.
// ---------------------------------------------------------------------------
__global__ __launch_bounds__(256)
void f_matvec_kernel(const float* __restrict__ g,
                     const float* __restrict__ w,
                     float* __restrict__ Fout) {
    __shared__ float4 w2s[625];           // w^2, float4-packed
    int tid = threadIdx.x;
    const float4* w4 = (const float4*)w;
    for (int j = tid; j < 625; j += 256) {
        float4 wv = w4[j];
        w2s[j] = make_float4(wv.x * wv.x, wv.y * wv.y, wv.z * wv.z, wv.w * wv.w);
    }
    __syncthreads();

    int warp = (blockIdx.x * 256 + tid) >> 5;
    int lane = tid & 31;
    if (warp >= NSQ) return;

    const float4* grow = (const float4*)(g + (size_t)warp * NSQ);
    float acc = 0.f;
    #pragma unroll 5
    for (int j = lane; j < 625; j += 32) {
        float4 gv = grow[j];
        float4 wv = w2s[j];
        acc = fmaf(gv.x, wv.x, acc);
        acc = fmaf(gv.y, wv.y, acc);
        acc = fmaf(gv.z, wv.z, acc);
        acc = fmaf(gv.w, wv.w, acc);
    }
    #pragma unroll
    for (int o = 16; o > 0; o >>= 1)
        acc += __shfl_down_sync(0xffffffffu, acc, o);
    if (lane == 0) Fout[warp] = acc;
}

// ---------------------------------------------------------------------------
// K2: Z[b,i] = p * mus[y_i[b], i]
// ---------------------------------------------------------------------------
__global__ void init_z_kernel(const int* __restrict__ y_i,
                              const float* __restrict__ mus,
                              float* __restrict__ Z) {
    int idx = blockIdx.x * blockDim.x + threadIdx.x;
    if (idx >= BB * NN) return;
    int b = idx / NN;
    int i = idx - b * NN;
    Z[idx] = (float)PP * mus[y_i[b] * NN + i];
}

// ---------------------------------------------------------------------------
// K3: block = 10 (b,p) units, flattened thread map (u = tid/50, i = tid%50).
//   z_i = sum_j exp2(na * F[i,j]) * a_j / sum_j exp2(na * F[i,j])
//   na = -alpha_t * log2(e), folded once per unit.
// ---------------------------------------------------------------------------
__global__ __launch_bounds__(MAIN_THREADS)
void main_kernel(const float* __restrict__ x,
                 const int*   __restrict__ x_i,
                 const float* __restrict__ mus,
                 const float* __restrict__ alphas,
                 const float* __restrict__ F,
                 float* __restrict__ Z) {
    __shared__ float Fs[NN * FSTRIDE];
    __shared__ float As[UNITS][NN];
    __shared__ float nal[UNITS];
    __shared__ int   ts[UNITS];

    int tid  = threadIdx.x;
    int gid0 = blockIdx.x * UNITS;
    int nu   = TOTAL_UNITS - gid0;        // units in this block
    if (nu > UNITS) nu = UNITS;

    for (int k = tid; k < NSQ; k += MAIN_THREADS) {
        int i = k / NN;
        int j = k - i * NN;
        Fs[i * FSTRIDE + j] = F[k];
    }
    if (tid < nu) {
        int t = x_i[gid0 + tid];
        ts[tid] = t;
        nal[tid] = -alphas[t] * 1.4426950408889634f;   // fold log2(e)
    }
    __syncthreads();

    for (int k = tid; k < nu * NN; k += MAIN_THREADS) {
        int u = k / NN;
        int j = k - u * NN;
        int unit = gid0 + u;
        As[u][j] = x[(size_t)(unit >> 5) * NN * PP + j * PP + (unit & 31)]
                 - mus[ts[u] * NN + j];
    }
    __syncthreads();

    if (tid < nu * NN) {
        int u = tid / NN;
        int i = tid - u * NN;
        float na = nal[u];
        const float* frow = &Fs[i * FSTRIDE];
        const float* av   = As[u];
        float acc = 0.f, s = 0.f;
        #pragma unroll
        for (int j = 0; j < NN; j++) {
            float e = ex2_approx(na * frow[j]);
            acc = fmaf(e, av[j], acc);
            s  += e;
        }
        int b = (gid0 + u) >> 5;
        atomicAdd(&Z[b * NN + i], __fdividef(acc, s));
    }
}

// ---------------------------------------------------------------------------
extern "C" void kernel_launch(void* const* d_in, const int* in_sizes, int n_in,
                              void* d_out, int out_size) {
    const float* x      = (const float*)d_in[0];  // [512,50,32]
    const int*   x_i    = (const int*)  d_in[1];  // [512,32]
    const int*   y_i    = (const int*)  d_in[2];  // [512]
    const float* g      = (const float*)d_in[3];  // [2500,2500]
    const float* w      = (const float*)d_in[4];  // [2500,1]
    const float* mus    = (const float*)d_in[5];  // [4000,50]
    const float* alphas = (const float*)d_in[6];  // [4000,1]

    float* out  = (float*)d_out;
    float* Z    = out;             // [512,50]
    float* Fout = out + BB * NN;   // [2500]

    f_matvec_kernel<<<(NSQ * 32 + 255) / 256, 256>>>(g, w, Fout);
    init_z_kernel<<<(BB * NN + 255) / 256, 256>>>(y_i, mus, Z);
    main_kernel<<<(TOTAL_UNITS + UNITS - 1) / UNITS, MAIN_THREADS>>>(x, x_i, mus, alphas, Fout, Z);
}

// round 7
// speedup vs baseline: 1.2116x; 1.1383x over previous
#include <cuda_runtime.h>

#define NN   50
#define PP   32
#define BB   512
#define NSQ  2500
#define FSTRIDE 54          // float2 stride 27, gcd(27,16)=1 -> conflict-free LDS.64
#define UNITS 10
#define MAIN_THREADS 512
#define TOTAL_UNITS (BB * PP)  // 16384

__device__ __forceinline__ float ex2_approx(float x) {
    float r;
    asm("ex2.approx.f32 %0, %1;" : "=f"(r) : "f"(x));
    return r;
}

// ---------------------------------------------------------------------------
// K1 v3: F[r] = sum_j g[r,j] * w[j]^2.
// Block = 256 threads = 8 warps = 4 rows x 2 half-row warps.
// Each warp register-batches 10 LDG.128 (loads-only loop -> MLP=10 guaranteed),
// then a separate LDS+FMA loop. Row pitch 10000 B = 625*16 -> float4 legal.
// ---------------------------------------------------------------------------
__global__ __launch_bounds__(256)
void f_matvec_kernel(const float* __restrict__ g,
                     const float* __restrict__ w,
                     float* __restrict__ Fout) {
    __shared__ float4 w2s[625];
    __shared__ float  part[8];
    int tid  = threadIdx.x;
    int lane = tid & 31;
    int wid  = tid >> 5;

    const float4* w4 = (const float4*)w;
    for (int j = tid; j < 625; j += 256) {
        float4 wv = w4[j];
        w2s[j] = make_float4(wv.x * wv.x, wv.y * wv.y, wv.z * wv.z, wv.w * wv.w);
    }
    __syncthreads();

    int row   = blockIdx.x * 4 + (wid >> 1);   // 625 blocks * 4 rows = 2500
    int h     = wid & 1;                       // half: 0 -> [0,313), 1 -> [313,625)
    int base  = h ? 313 : 0;
    int bound = h ? 625 : 313;

    const float4* grow = (const float4*)g + (size_t)row * 625;

    // Phase 1: loads only (front-batched, 10 independent LDG.128)
    float4 rbuf[10];
    int    idxs[10];
    #pragma unroll
    for (int k = 0; k < 10; k++) {
        int idx = base + lane + 32 * k;
        idxs[k] = idx;
        rbuf[k] = (idx < bound) ? grow[idx]
                                : make_float4(0.f, 0.f, 0.f, 0.f);
    }

    // Phase 2: LDS + FMA
    float acc = 0.f;
    #pragma unroll
    for (int k = 0; k < 10; k++) {
        int idx = idxs[k];
        float4 wv = (idx < bound) ? w2s[idx] : make_float4(0.f, 0.f, 0.f, 0.f);
        acc = fmaf(rbuf[k].x, wv.x, acc);
        acc = fmaf(rbuf[k].y, wv.y, acc);
        acc = fmaf(rbuf[k].z, wv.z, acc);
        acc = fmaf(rbuf[k].w, wv.w, acc);
    }

    #pragma unroll
    for (int o = 16; o > 0; o >>= 1)
        acc += __shfl_down_sync(0xffffffffu, acc, o);
    if (lane == 0) part[wid] = acc;
    __syncthreads();
    if (tid < 4)
        Fout[blockIdx.x * 4 + tid] = part[2 * tid] + part[2 * tid + 1];
}

// ---------------------------------------------------------------------------
// K2: Z[b,i] = p * mus[y_i[b], i]
// ---------------------------------------------------------------------------
__global__ void init_z_kernel(const int* __restrict__ y_i,
                              const float* __restrict__ mus,
                              float* __restrict__ Z) {
    int idx = blockIdx.x * blockDim.x + threadIdx.x;
    if (idx >= BB * NN) return;
    int b = idx / NN;
    int i = idx - b * NN;
    Z[idx] = (float)PP * mus[y_i[b] * NN + i];
}

// ---------------------------------------------------------------------------
// K3: block = 10 (b,p) units, flattened map (u = tid/50, i = tid%50).
// j-loop consumes float2 pairs -> half the LDS instructions; MUFU-bound.
// ---------------------------------------------------------------------------
__global__ __launch_bounds__(MAIN_THREADS)
void main_kernel(const float* __restrict__ x,
                 const int*   __restrict__ x_i,
                 const float* __restrict__ mus,
                 const float* __restrict__ alphas,
                 const float* __restrict__ F,
                 float* __restrict__ Z) {
    __shared__ float Fs[NN * FSTRIDE];
    __shared__ __align__(8) float As[UNITS][52];   // row stride 208 B, 8-aligned
    __shared__ float nal[UNITS];
    __shared__ int   ts[UNITS];

    int tid  = threadIdx.x;
    int gid0 = blockIdx.x * UNITS;
    int nu   = TOTAL_UNITS - gid0;
    if (nu > UNITS) nu = UNITS;

    for (int k = tid; k < NSQ; k += MAIN_THREADS) {
        int i = k / NN;
        int j = k - i * NN;
        Fs[i * FSTRIDE + j] = F[k];
    }
    if (tid < nu) {
        int t = x_i[gid0 + tid];
        ts[tid] = t;
        nal[tid] = -alphas[t] * 1.4426950408889634f;   // fold log2(e)
    }
    __syncthreads();

    for (int k = tid; k < nu * NN; k += MAIN_THREADS) {
        int u = k / NN;
        int j = k - u * NN;
        int unit = gid0 + u;
        As[u][j] = x[(size_t)(unit >> 5) * NN * PP + j * PP + (unit & 31)]
                 - mus[ts[u] * NN + j];
    }
    __syncthreads();

    if (tid < nu * NN) {
        int u = tid / NN;
        int i = tid - u * NN;
        float na = nal[u];
        const float2* frow2 = (const float2*)&Fs[i * FSTRIDE];
        const float2* av2   = (const float2*)As[u];
        float acc = 0.f, s = 0.f;
        #pragma unroll
        for (int jj = 0; jj < NN / 2; jj++) {
            float2 fv = frow2[jj];
            float2 av = av2[jj];
            float e0 = ex2_approx(na * fv.x);
            acc = fmaf(e0, av.x, acc);
            s  += e0;
            float e1 = ex2_approx(na * fv.y);
            acc = fmaf(e1, av.y, acc);
            s  += e1;
        }
        int b = (gid0 + u) >> 5;
        atomicAdd(&Z[b * NN + i], __fdividef(acc, s));
    }
}

// ---------------------------------------------------------------------------
extern "C" void kernel_launch(void* const* d_in, const int* in_sizes, int n_in,
                              void* d_out, int out_size) {
    const float* x      = (const float*)d_in[0];  // [512,50,32]
    const int*   x_i    = (const int*)  d_in[1];  // [512,32]
    const int*   y_i    = (const int*)  d_in[2];  // [512]
    const float* g      = (const float*)d_in[3];  // [2500,2500]
    const float* w      = (const float*)d_in[4];  // [2500,1]
    const float* mus    = (const float*)d_in[5];  // [4000,50]
    const float* alphas = (const float*)d_in[6];  // [4000,1]

    float* out  = (float*)d_out;
    float* Z    = out;             // [512,50]
    float* Fout = out + BB * NN;   // [2500]

    f_matvec_kernel<<<625, 256>>>(g, w, Fout);
    init_z_kernel<<<(BB * NN + 255) / 256, 256>>>(y_i, mus, Z);
    main_kernel<<<(TOTAL_UNITS + UNITS - 1) / UNITS, MAIN_THREADS>>>(x, x_i, mus, alphas, Fout, Z);
}